// round 16
// baseline (speedup 1.0000x reference)
#include <cuda_runtime.h>
#include <cstdint>
#include <cstddef>

#define B_PTS 256
#define DIM 128
#define N_BANK 500000
#define N_HALVES 7813         /* ceil(500000/64) */
#define GRID_GEMM 148
#define THREADS 256
#define K2E 20.609929155556618f   /* log2(e)/0.07 */
#define PADF_A 136            /* A row stride (words): conflict-free LDS.64 pairs */
#define PADF_B 132            /* B row stride (words): conflict-free LDS.32 frags */

/* Schraudolph exp2: bitcast<float>((int)(s*K2E*2^23 + (127*2^23 - c))) ~= exp(s/T) */
#define SCHA 172888616.0f     /* K2E * 2^23 */
#define SCHB 1064992447.0f    /* 127*2^23 - 360769 */
#define SCHMAX 2130706432.0f  /* 0x7F000000 */

static __device__ float g_part[GRID_GEMM * 2 * B_PTS];
static __device__ int g_done = 0;

// ---------------- helpers ----------------
__device__ __forceinline__ uint32_t smem_u32(const void* p) {
    uint32_t a;
    asm("{ .reg .u64 t; cvta.to.shared.u64 t, %1; cvt.u32.u64 %0, t; }" : "=r"(a) : "l"(p));
    return a;
}
__device__ __forceinline__ float fast_ex2(float x) {
    float y; asm("ex2.approx.ftz.f32 %0, %1;" : "=f"(y) : "f"(x)); return y;
}
__device__ __forceinline__ float approx_expT(float s) {
    float t = fmaf(s, SCHA, SCHB);
    t = fmaxf(t, 0.0f);
    t = fminf(t, SCHMAX);
    return __int_as_float(__float2int_rn(t));
}
__device__ __forceinline__ void cp_async16(uint32_t dst, const void* src, int sz) {
    asm volatile("cp.async.cg.shared.global [%0], [%1], 16, %2;"
                 :: "r"(dst), "l"(src), "r"(sz) : "memory");
}
#define CP_COMMIT() asm volatile("cp.async.commit_group;" ::: "memory")
#define CP_WAIT1()  asm volatile("cp.async.wait_group 1;" ::: "memory")

// tf32 mma: D(16x8) += A(16x8) * B(8x8).  A row-major, B col-major.
__device__ __forceinline__ void mma_tf32(float c[4], const uint32_t a[4], const uint32_t b[2]) {
    asm volatile(
        "mma.sync.aligned.m16n8k8.row.col.f32.tf32.tf32.f32 "
        "{%0,%1,%2,%3}, {%4,%5,%6,%7}, {%8,%9}, {%0,%1,%2,%3};"
        : "+f"(c[0]), "+f"(c[1]), "+f"(c[2]), "+f"(c[3])
        : "r"(a[0]), "r"(a[1]), "r"(a[2]), "r"(a[3]), "r"(b[0]), "r"(b[1]));
}

// SMEM: A permuted [256][136] (resident), two B half-buffers [64][132],
// then 8 per-warp transpose patches of 8x34 words.
#define SMEM_A_FLOATS (B_PTS * PADF_A)        /* 34816 */
#define SMEM_B_FLOATS (64 * PADF_B)           /* 8448 */
#define PATCH_W 34
#define PATCH_FLOATS (8 * PATCH_W)            /* 272 words per warp */
#define SMEM_TOTAL_BYTES ((SMEM_A_FLOATS + 2 * SMEM_B_FLOATS + 8 * PATCH_FLOATS) * 4) /* 215552 */

__device__ __forceinline__ void load_half(const float* __restrict__ bank, float* sBh,
                                          int baserow, int tid) {
    // 2048 16B chunks (64 rows x 32 chunks), 256 threads -> 8 iterations.
    #pragma unroll
    for (int it = 0; it < 8; it++) {
        int c = it * THREADS + tid;
        int r = c >> 5;
        int ch = c & 31;
        int grow = baserow + r;
        int ok = (grow < N_BANK);
        const float* src = bank + (size_t)(ok ? grow : 0) * DIM + ch * 4;
        uint32_t dst = smem_u32(sBh + r * PADF_B + ch * 4);
        cp_async16(dst, src, ok ? 16 : 0);
    }
}

// A column permutation: within each 8-col block store order [0,4,1,5,2,6,3,7]
// so fragment pairs (k, k+4) are adjacent -> LDS.64.
__device__ __forceinline__ int a_perm(int c) {
    return (c & ~7) + ((c & 3) << 1) + ((c >> 2) & 1);
}

// ---------------- single fused kernel ----------------
// 256 threads = 8 warps.  Warp tile 64M x 32N (4 M-positions x 2 N-positions):
// fragment bytes/output = 512*(1/64 + 1/32) = 24B (vs 32B at 32x32) -> -17% L1.
// 256 threads => 255-reg budget: c[4][4][4]=64 accum regs with zero spill risk.
__global__ void __launch_bounds__(THREADS, 1)
hn_fused_kernel(const float* __restrict__ points, const int* __restrict__ pidx,
                const float* __restrict__ bank, float* __restrict__ out, int off) {
    extern __shared__ float sm[];
    float* sA = sm;
    float* sB0 = sm + SMEM_A_FLOATS;
    float* sB1 = sB0 + SMEM_B_FLOATS;
    float* sTr = sB1 + SMEM_B_FLOATS;   // 8 warp patches

    const int tid = threadIdx.x;
    const int bid = blockIdx.x;
    const int wid = tid >> 5;
    const int lane = tid & 31;
    const int grp = lane >> 2;          // 0..7
    const int tg = lane & 3;            // 0..3
    const int mq = wid & 3;             // which 64-row block of points
    const int nq = wid >> 2;            // which 32-col half of the 64-col B buffer
    const int mwarp = mq * 64;

    // ---- prologue: normalize points into sA (permuted layout) ----
    {
        const int row = tid;
        const float4* src = reinterpret_cast<const float4*>(points) + row * 32;
        float ss = 0.0f;
        #pragma unroll 8
        for (int i = 0; i < 32; i++) {
            float4 q = src[i];
            ss += q.x * q.x + q.y * q.y + q.z * q.z + q.w * q.w;
        }
        float inv = rsqrtf(ss);
        float* dst = sA + row * PADF_A;
        #pragma unroll 8
        for (int i = 0; i < 32; i++) {
            float4 q = src[i];
            uint32_t ux, uy, uz, uw;
            asm("cvt.rna.tf32.f32 %0, %1;" : "=r"(ux) : "f"(q.x * inv));
            asm("cvt.rna.tf32.f32 %0, %1;" : "=r"(uy) : "f"(q.y * inv));
            asm("cvt.rna.tf32.f32 %0, %1;" : "=r"(uz) : "f"(q.z * inv));
            asm("cvt.rna.tf32.f32 %0, %1;" : "=r"(uw) : "f"(q.w * inv));
            dst[a_perm(i * 4 + 0)] = __uint_as_float(ux);
            dst[a_perm(i * 4 + 1)] = __uint_as_float(uy);
            dst[a_perm(i * 4 + 2)] = __uint_as_float(uz);
            dst[a_perm(i * 4 + 3)] = __uint_as_float(uw);
        }
    }

    // ---- B pipeline prologue (half-granular striping: half h = bid + g*GRID) ----
    load_half(bank, sB0, bid * 64, tid);
    CP_COMMIT();
    {
        int h1 = bid + GRID_GEMM;
        if (h1 < N_HALVES) load_half(bank, sB1, h1 * 64, tid);
        CP_COMMIT();
    }

    const int n_h = (N_HALVES - 1 - bid) / GRID_GEMM + 1;   // halves this CTA owns

    // per-thread denominator partials: [mt][hi] -> row mwarp + mt*16 + grp + hi*8
    float accR[4][2] = {{0.f, 0.f}, {0.f, 0.f}, {0.f, 0.f}, {0.f, 0.f}};

    float* const patch = sTr + wid * PATCH_FLOATS;
    const uint2* Au2 = reinterpret_cast<const uint2*>(sA);

    for (int g = 0; g < n_h; g++) {
        const int buf = g & 1;
        float* Bb = buf ? sB1 : sB0;
        CP_WAIT1();
        __syncthreads();

        const int h = bid + g * GRID_GEMM;
        const int gnb = h * 64;                    // global n base of this half
        int nv = N_BANK - gnb; if (nv > 64) nv = 64;   // 64 or 32 (tail)

        float c[4][4][4];
        {
            #pragma unroll
            for (int mt = 0; mt < 4; mt++)
                #pragma unroll
                for (int nt = 0; nt < 4; nt++)
                    #pragma unroll
                    for (int q = 0; q < 4; q++) c[mt][nt][q] = 0.f;

            const uint32_t* Bu = reinterpret_cast<const uint32_t*>(Bb);

            #pragma unroll 2
            for (int kt = 0; kt < 16; kt++) {
                // A fragments via LDS.64 from permuted layout.
                uint32_t a[4][4];
                #pragma unroll
                for (int mt = 0; mt < 4; mt++) {
                    int ai = (mwarp + mt * 16 + grp) * (PADF_A / 2) + kt * 4 + tg;
                    uint2 p0 = Au2[ai];                      // (k0, k0+4)
                    uint2 p1 = Au2[ai + 8 * (PADF_A / 2)];   // rows +8
                    a[mt][0] = p0.x;
                    a[mt][2] = p0.y;
                    a[mt][1] = p1.x;
                    a[mt][3] = p1.y;
                }
                const int k0 = kt * 8 + tg;
                uint32_t b[4][2];
                #pragma unroll
                for (int nt = 0; nt < 4; nt++) {
                    int bi = (nq * 32 + nt * 8 + grp) * PADF_B + k0;
                    b[nt][0] = Bu[bi];
                    b[nt][1] = Bu[bi + 4];
                }
                #pragma unroll
                for (int mt = 0; mt < 4; mt++)
                    #pragma unroll
                    for (int nt = 0; nt < 4; nt++)
                        mma_tf32(c[mt][nt], a[mt], b[nt]);
            }
        }

        __syncthreads();   // all warps done reading buffer g
        // ---- issue load for half g+2 into this buffer (overlaps epilogue) ----
        {
            const int h2 = bid + (g + 2) * GRID_GEMM;
            if (h2 < N_HALVES)
                load_half(bank, (g & 1) ? sB1 : sB0, h2 * 64, tid);
            CP_COMMIT();
        }

        // ---- epilogue: exp-accumulate + coalesced stores via warp transpose ----
        if (nq * 32 < nv) {               // nv in {32,64}: whole 32-col slice valid
            #pragma unroll
            for (int mt = 0; mt < 4; mt++) {
                #pragma unroll
                for (int hi = 0; hi < 2; hi++) {
                    #pragma unroll
                    for (int nt = 0; nt < 4; nt++) {
                        float v0 = c[mt][nt][hi * 2 + 0];
                        float v1 = c[mt][nt][hi * 2 + 1];
                        accR[mt][hi] += approx_expT(v0) + approx_expT(v1);
                        *reinterpret_cast<float2*>(patch + grp * PATCH_W + nt * 8 + tg * 2) =
                            make_float2(v0, v1);
                    }
                    __syncwarp();
                    float vals[8];
                    #pragma unroll
                    for (int r = 0; r < 8; r++)
                        vals[r] = patch[r * PATCH_W + lane];
                    const int grow = mwarp + mt * 16 + hi * 8;
                    float* pout = out + off + (size_t)grow * N_BANK + gnb + nq * 32 + lane;
                    #pragma unroll
                    for (int r = 0; r < 8; r++)
                        pout[(size_t)r * N_BANK] = vals[r];
                    __syncwarp();
                }
            }
        }
    }

    // ---- reduce denominator partials across the 4 lanes sharing a row ----
    #pragma unroll
    for (int mt = 0; mt < 4; mt++)
        #pragma unroll
        for (int hi = 0; hi < 2; hi++) {
            float v = accR[mt][hi];
            v += __shfl_xor_sync(0xFFFFFFFFu, v, 1);
            v += __shfl_xor_sync(0xFFFFFFFFu, v, 2);
            if (tg == 0) {
                int row = mwarp + mt * 16 + grp + hi * 8;
                g_part[(bid * 2 + nq) * B_PTS + row] = v;
            }
        }

    // ---- last-CTA finalize ----
    __shared__ int s_last, s_is64;
    __shared__ float sh[B_PTS];
    __threadfence();
    __syncthreads();                    // all warps' g_part stores done + fenced
    if (tid == 0) s_last = (atomicAdd(&g_done, 1) == GRID_GEMM - 1);
    __syncthreads();
    if (!s_last) return;
    __threadfence();

    if (tid == 0) {
        int z = 1;
        for (int i = 1; i < 2 * B_PTS; i += 2)
            if (pidx[i] != 0) { z = 0; break; }
        s_is64 = z;
    }
    __syncthreads();

    {
        const int b = tid;
        long long idx = s_is64 ? ((const long long*)pidx)[b] : (long long)pidx[b];
        float d = 0.0f;
        for (int c = 0; c < 2 * GRID_GEMM; c++) d += g_part[c * B_PTS + b];

        // exact fp32 positive similarity: dot(normalize(points[b]), bank[idx])
        const float4* pp = reinterpret_cast<const float4*>(points) + b * 32;
        const float4* bb = reinterpret_cast<const float4*>(bank) + (size_t)idx * 32;
        float ss = 0.0f, dp = 0.0f;
        #pragma unroll 8
        for (int i = 0; i < 32; i++) {
            float4 q = pp[i]; float4 r = bb[i];
            ss += q.x * q.x + q.y * q.y + q.z * q.z + q.w * q.w;
            dp += q.x * r.x + q.y * r.y + q.z * r.z + q.w * r.w;
        }
        float sim = dp * rsqrtf(ss);
        float pos = fast_ex2(sim * K2E);
        sh[b] = -logf(pos / d + 1e-7f);
    }
    __syncthreads();
    for (int o = 128; o > 0; o >>= 1) {
        if (tid < o) sh[tid] += sh[tid + o];
        __syncthreads();
    }
    if (tid == 0) {
        if (off) out[0] = sh[0] * (1.0f / 256.0f);
        g_done = 0;   // reset for next (graph-replayed) call: deterministic
    }
}

// ---------------- launch ----------------
extern "C" void kernel_launch(void* const* d_in, const int* in_sizes, int n_in,
                              void* d_out, int out_size) {
    const float* points = (const float*)d_in[0];
    const int* pidx = (const int*)d_in[1];
    const float* bank = (const float*)d_in[2];
    float* out = (float*)d_out;

    int off = (out_size > 128000000) ? 1 : 0;   // loss scalar precedes sims

    cudaFuncSetAttribute(hn_fused_kernel, cudaFuncAttributeMaxDynamicSharedMemorySize,
                         SMEM_TOTAL_BYTES);

    hn_fused_kernel<<<GRID_GEMM, THREADS, SMEM_TOTAL_BYTES>>>(points, pidx, bank, out, off);
}

// round 17
// speedup vs baseline: 1.3921x; 1.3921x over previous
#include <cuda_runtime.h>
#include <cstdint>
#include <cstddef>

#define B_PTS 256
#define DIM 128
#define N_BANK 500000
#define N_HALVES 7813         /* ceil(500000/64) */
#define GRID_GEMM 148
#define THREADS 512
#define K2E 20.609929155556618f   /* log2(e)/0.07 */

/* Schraudolph exp2: bitcast<float>((int)(s*K2E*2^23 + (127*2^23 - c))) ~= exp(s/T) */
#define SCHA 172888616.0f     /* K2E * 2^23 */
#define SCHB 1064992447.0f    /* 127*2^23 - 360769 */
#define SCHMAX 2130706432.0f  /* 0x7F000000 */

/* fp16 SMEM layout: one b32 = pair of halves (k even, k odd).  Row stride
   SA2 uint2 (= 2*SA2 b32 = 8*SA2 bytes).  36 chosen so LDS.64 fragment loads
   are bank-conflict-free (banks (8*grp+2*tg)%32 all distinct per 16-lane phase). */
#define SA2 36
#define A_U32 (B_PTS * 2 * SA2)       /* 18432 b32 */
#define B_U32 (64 * 2 * SA2)          /* 4608 b32 per buffer */
#define PATCH_W 34
#define PATCH_FLOATS (8 * PATCH_W)
#define SMEM_TOTAL_BYTES ((A_U32 + 2 * B_U32 + 16 * PATCH_FLOATS) * 4)   /* 127616 */

static __device__ float g_part[GRID_GEMM * 2 * B_PTS];
static __device__ int g_done = 0;

// ---------------- helpers ----------------
__device__ __forceinline__ float fast_ex2(float x) {
    float y; asm("ex2.approx.ftz.f32 %0, %1;" : "=f"(y) : "f"(x)); return y;
}
__device__ __forceinline__ float approx_expT(float s) {
    float t = fmaf(s, SCHA, SCHB);
    t = fmaxf(t, 0.0f);
    t = fminf(t, SCHMAX);
    return __int_as_float(__float2int_rn(t));
}
// d = {hi: conv(hi), lo: conv(lo)} — PTX cvt packs src1 into the upper half.
__device__ __forceinline__ uint32_t pack_f16x2(float lo, float hi) {
    uint32_t d;
    asm("cvt.rn.f16x2.f32 %0, %1, %2;" : "=r"(d) : "f"(hi), "f"(lo));
    return d;
}
// pair-permutation within an 8-pair (kt) block: stored order [0,4,1,5,2,6,3,7]
__device__ __forceinline__ int perm_pair(int q) {
    return (q & ~7) + ((q & 3) << 1) + ((q >> 2) & 1);
}

// fp16 mma: D(16x8,f32) += A(16x16,f16) * B(16x8,f16).  A row-major, B col-major.
__device__ __forceinline__ void mma_f16(float c[4], const uint32_t a[4], const uint32_t b[2]) {
    asm volatile(
        "mma.sync.aligned.m16n8k16.row.col.f32.f16.f16.f32 "
        "{%0,%1,%2,%3}, {%4,%5,%6,%7}, {%8,%9}, {%0,%1,%2,%3};"
        : "+f"(c[0]), "+f"(c[1]), "+f"(c[2]), "+f"(c[3])
        : "r"(a[0]), "r"(a[1]), "r"(a[2]), "r"(a[3]), "r"(b[0]), "r"(b[1]));
}

// Load one 64-row half into registers (16 floats / thread); issued one half
// ahead so DRAM latency hides under the previous mainloop.
__device__ __forceinline__ void ldg_half(const float* __restrict__ bank, int gnb,
                                         int tid, float4 v[4]) {
    int r = tid >> 3, c8 = tid & 7;
    long long grow = gnb + r;
    if (grow >= N_BANK) grow = N_BANK - 1;
    const float4* src = reinterpret_cast<const float4*>(bank + (size_t)grow * DIM + c8 * 16);
    v[0] = src[0]; v[1] = src[1]; v[2] = src[2]; v[3] = src[3];
}

// Convert held registers to fp16 pairs and store permuted into a B buffer.
__device__ __forceinline__ void cvt_store_half(uint32_t* sBh, int tid, const float4 v[4]) {
    int r = tid >> 3, c8 = tid & 7;
    uint32_t pr[8];
    #pragma unroll
    for (int i = 0; i < 4; i++) {
        pr[2 * i]     = pack_f16x2(v[i].x, v[i].y);
        pr[2 * i + 1] = pack_f16x2(v[i].z, v[i].w);
    }
    uint2* dst = reinterpret_cast<uint2*>(sBh) + r * SA2 + c8 * 4;
    #pragma unroll
    for (int j = 0; j < 4; j++)
        dst[j] = make_uint2(pr[j], pr[j + 4]);   // stored block order [p0,p4,p1,p5,...]
}

// ---------------- single fused kernel ----------------
__global__ void __launch_bounds__(THREADS, 1)
hn_fused_kernel(const float* __restrict__ points, const int* __restrict__ pidx,
                const float* __restrict__ bank, float* __restrict__ out, int off) {
    extern __shared__ uint32_t smu[];
    uint32_t* sAh = smu;                         // A fp16, permuted pairs
    uint32_t* sB0 = smu + A_U32;
    uint32_t* sB1 = sB0 + B_U32;
    float* sTr = reinterpret_cast<float*>(sB1 + B_U32);   // 16 warp patches

    const int tid = threadIdx.x;
    const int bid = blockIdx.x;
    const int wid = tid >> 5;
    const int lane = tid & 31;
    const int grp = lane >> 2;          // 0..7
    const int tg = lane & 3;            // 0..3
    const int mq = wid & 7;             // which 32-row block of points
    const int nh = wid >> 3;            // which 32-col half of the 64-col B buffer
    const int mwarp = mq * 32;

    // ---- prologue: normalize points -> fp16 permuted A ----
    if (tid < B_PTS) {
        const int row = tid;
        const float4* src = reinterpret_cast<const float4*>(points) + row * 32;
        float ss = 0.0f;
        #pragma unroll 8
        for (int i = 0; i < 32; i++) {
            float4 q = src[i];
            ss += q.x * q.x + q.y * q.y + q.z * q.z + q.w * q.w;
        }
        float inv = rsqrtf(ss);
        uint32_t* dst = sAh + row * 2 * SA2;
        #pragma unroll 8
        for (int i = 0; i < 32; i++) {
            float4 q = src[i];
            dst[perm_pair(2 * i)]     = pack_f16x2(q.x * inv, q.y * inv);
            dst[perm_pair(2 * i + 1)] = pack_f16x2(q.z * inv, q.w * inv);
        }
    }

    float4 v[4];
    ldg_half(bank, bid * 64, tid, v);           // half h0
    __syncthreads();                            // A visible
    cvt_store_half(sB0, tid, v);
    {
        int h1 = bid + GRID_GEMM;
        if (h1 < N_HALVES) ldg_half(bank, h1 * 64, tid, v);
    }
    __syncthreads();                            // buf0 visible

    const int n_h = (N_HALVES - 1 - bid) / GRID_GEMM + 1;

    // per-thread denominator partials: [mt][hi] -> row mwarp + mt*16 + grp + hi*8
    float accR[2][2] = {{0.f, 0.f}, {0.f, 0.f}};
    float* const patch = sTr + wid * PATCH_FLOATS;
    const uint2* Au2 = reinterpret_cast<const uint2*>(sAh);

    for (int g = 0; g < n_h; g++) {
        const uint2* Bu2 = reinterpret_cast<const uint2*>((g & 1) ? sB1 : sB0);
        const int h = bid + g * GRID_GEMM;
        const int gnb = h * 64;
        int nv = N_BANK - gnb; if (nv > 64) nv = 64;   // 64 or 32 (tail)

        float c[2][4][4];
        #pragma unroll
        for (int mt = 0; mt < 2; mt++)
            #pragma unroll
            for (int nt = 0; nt < 4; nt++)
                #pragma unroll
                for (int q = 0; q < 4; q++) c[mt][nt][q] = 0.f;

        #pragma unroll
        for (int kt = 0; kt < 8; kt++) {
            // A fragments: uint2 -> (a0,a2) and rows+8 -> (a1,a3)
            uint32_t a[2][4];
            #pragma unroll
            for (int mt = 0; mt < 2; mt++) {
                int ai = (mwarp + mt * 16 + grp) * SA2 + kt * 4 + tg;
                uint2 p0 = Au2[ai];
                uint2 p1 = Au2[ai + 8 * SA2];
                a[mt][0] = p0.x; a[mt][2] = p0.y;
                a[mt][1] = p1.x; a[mt][3] = p1.y;
            }
            uint32_t b[4][2];
            #pragma unroll
            for (int nt = 0; nt < 4; nt++) {
                int bi = (nh * 32 + nt * 8 + grp) * SA2 + kt * 4 + tg;
                uint2 pb = Bu2[bi];
                b[nt][0] = pb.x; b[nt][1] = pb.y;
            }
            #pragma unroll
            for (int mt = 0; mt < 2; mt++)
                #pragma unroll
                for (int nt = 0; nt < 4; nt++)
                    mma_f16(c[mt][nt], a[mt], b[nt]);
        }

        // ---- epilogue: exp-accumulate + coalesced stores via warp transpose ----
        if (nh * 32 < nv) {               // nv in {32,64}: whole 32-col slice valid
            #pragma unroll
            for (int mt = 0; mt < 2; mt++) {
                #pragma unroll
                for (int hi = 0; hi < 2; hi++) {
                    #pragma unroll
                    for (int nt = 0; nt < 4; nt++) {
                        float v0 = c[mt][nt][hi * 2 + 0];
                        float v1 = c[mt][nt][hi * 2 + 1];
                        accR[mt][hi] += approx_expT(v0) + approx_expT(v1);
                        *reinterpret_cast<float2*>(patch + grp * PATCH_W + nt * 8 + tg * 2) =
                            make_float2(v0, v1);
                    }
                    __syncwarp();
                    float vals[8];
                    #pragma unroll
                    for (int r = 0; r < 8; r++)
                        vals[r] = patch[r * PATCH_W + lane];
                    const int grow = mwarp + mt * 16 + hi * 8;
                    float* pout = out + off + (size_t)grow * N_BANK + gnb + nh * 32 + lane;
                    #pragma unroll
                    for (int r = 0; r < 8; r++)
                        pout[(size_t)r * N_BANK] = vals[r];
                    __syncwarp();
                }
            }
        }

        // ---- tail: convert half g+1 (other buffer), prefetch half g+2 ----
        if (g + 1 < n_h) {
            cvt_store_half((g & 1) ? sB0 : sB1, tid, v);   // writes buffer (g+1)&1
            int h2 = bid + (g + 2) * GRID_GEMM;
            if (h2 < N_HALVES) ldg_half(bank, h2 * 64, tid, v);
            __syncthreads();            // converted data visible for mainloop g+1
        }
    }

    // ---- reduce denominator partials across the 4 lanes sharing a row ----
    #pragma unroll
    for (int mt = 0; mt < 2; mt++)
        #pragma unroll
        for (int hi = 0; hi < 2; hi++) {
            float vv = accR[mt][hi];
            vv += __shfl_xor_sync(0xFFFFFFFFu, vv, 1);
            vv += __shfl_xor_sync(0xFFFFFFFFu, vv, 2);
            if (tg == 0) {
                int row = mwarp + mt * 16 + grp + hi * 8;
                g_part[(bid * 2 + nh) * B_PTS + row] = vv;
            }
        }

    // ---- last-CTA finalize ----
    __shared__ int s_last, s_is64;
    __shared__ float sh[B_PTS];
    __threadfence();
    __syncthreads();
    if (tid == 0) s_last = (atomicAdd(&g_done, 1) == GRID_GEMM - 1);
    __syncthreads();
    if (!s_last) return;
    __threadfence();

    if (tid == 0) {
        int z = 1;
        for (int i = 1; i < 2 * B_PTS; i += 2)
            if (pidx[i] != 0) { z = 0; break; }
        s_is64 = z;
    }
    __syncthreads();

    if (tid < B_PTS) {
        const int b = tid;
        long long idx = s_is64 ? ((const long long*)pidx)[b] : (long long)pidx[b];
        float d = 0.0f;
        for (int c2 = 0; c2 < 2 * GRID_GEMM; c2++) d += g_part[c2 * B_PTS + b];

        // exact fp32 positive similarity: dot(normalize(points[b]), bank[idx])
        const float4* pp = reinterpret_cast<const float4*>(points) + b * 32;
        const float4* bb = reinterpret_cast<const float4*>(bank) + (size_t)idx * 32;
        float ss = 0.0f, dp = 0.0f;
        #pragma unroll 8
        for (int i = 0; i < 32; i++) {
            float4 q = pp[i]; float4 r = bb[i];
            ss += q.x * q.x + q.y * q.y + q.z * q.z + q.w * q.w;
            dp += q.x * r.x + q.y * r.y + q.z * r.z + q.w * r.w;
        }
        float sim = dp * rsqrtf(ss);
        float pos = fast_ex2(sim * K2E);
        sh[b] = -logf(pos / d + 1e-7f);
    }
    __syncthreads();
    for (int o = 128; o > 0; o >>= 1) {
        if (tid < o) sh[tid] += sh[tid + o];
        __syncthreads();
    }
    if (tid == 0) {
        if (off) out[0] = sh[0] * (1.0f / 256.0f);
        g_done = 0;   // reset for next (graph-replayed) call: deterministic
    }
}

// ---------------- launch ----------------
extern "C" void kernel_launch(void* const* d_in, const int* in_sizes, int n_in,
                              void* d_out, int out_size) {
    const float* points = (const float*)d_in[0];
    const int* pidx = (const int*)d_in[1];
    const float* bank = (const float*)d_in[2];
    float* out = (float*)d_out;

    int off = (out_size > 128000000) ? 1 : 0;   // loss scalar precedes sims

    cudaFuncSetAttribute(hn_fused_kernel, cudaFuncAttributeMaxDynamicSharedMemorySize,
                         SMEM_TOTAL_BYTES);

    hn_fused_kernel<<<GRID_GEMM, THREADS, SMEM_TOTAL_BYTES>>>(points, pidx, bank, out, off);
}